// round 4
// baseline (speedup 1.0000x reference)
#include <cuda_runtime.h>

// Batched per-object 3-layer MLP — 2 sequential kernels, no inter-CTA waiting.
//
//   K1: y1 = W1 @ x + b1                       (256 MB stream)
//   K2: y2 rows = sigmoid(W2@y1+b2); each CTA folds its 32-row partial of
//       W3 . y2 into g_acc[o]; the LAST chunk (atomic counter) applies the
//       final sigmoid and writes out[o].       (512 MB stream)
//
// No y2 staging, no third kernel. Weights read exactly once, coalesced float4.

#define N_OBJ_  2048
#define IN_DIM_ 128
#define MID_    256

__device__ float    g_y1[N_OBJ_ * MID_];
__device__ float    g_acc[N_OBJ_];    // zero-init; finalizer resets each replay
__device__ unsigned g_cnt[N_OBJ_];    // zero-init; finalizer resets each replay

__device__ __forceinline__ float warp_sum(float v) {
#pragma unroll
    for (int off = 16; off > 0; off >>= 1)
        v += __shfl_xor_sync(0xffffffffu, v, off);
    return v;
}

__device__ __forceinline__ float sigmoidf_(float t) {
    return 1.0f / (1.0f + __expf(-t));
}

// ---- K1: 32 rows of y1 per CTA (4 warps x 8 rows) ----
__global__ __launch_bounds__(128, 16)
void k1_fc1(const float* __restrict__ x,
            const float* __restrict__ W1,
            const float* __restrict__ b1)
{
    const int o     = blockIdx.x >> 3;
    const int chunk = blockIdx.x & 7;
    const int warp  = threadIdx.x >> 5;
    const int lane  = threadIdx.x & 31;

    const float4 xv =
        reinterpret_cast<const float4*>(x + (size_t)o * IN_DIM_)[lane];
    const float* W1o = W1 + (size_t)o * MID_ * IN_DIM_;
    const int row0 = chunk * 32 + warp * 8;

#pragma unroll
    for (int j = 0; j < 8; ++j) {
        const int row = row0 + j;
        const float4 w =
            reinterpret_cast<const float4*>(W1o + (size_t)row * IN_DIM_)[lane];
        float s = fmaf(w.x, xv.x, fmaf(w.y, xv.y, fmaf(w.z, xv.z, w.w * xv.w)));
        s = warp_sum(s);
        if (lane == 0)
            g_y1[o * MID_ + row] = s + b1[o * MID_ + row];
    }
}

// ---- K2: 32 rows of y2 per CTA + W3 partial; last chunk finalizes ----
__global__ __launch_bounds__(128, 16)
void k2_fc2(const float* __restrict__ W2,
            const float* __restrict__ b2,
            const float* __restrict__ W3,
            const float* __restrict__ b3,
            float* __restrict__ out)
{
    const int o     = blockIdx.x >> 3;
    const int chunk = blockIdx.x & 7;
    const int warp  = threadIdx.x >> 5;
    const int lane  = threadIdx.x & 31;

    const float4* y1v = reinterpret_cast<const float4*>(g_y1 + o * MID_);
    const float4 ya = y1v[lane];
    const float4 yb = y1v[32 + lane];

    const float* W2o = W2 + (size_t)o * MID_ * MID_;
    const float* W3o = W3 + (size_t)o * MID_;
    const int row0 = chunk * 32 + warp * 8;

    float p = 0.0f;   // lane-0 partial of W3 . y2 over this warp's 8 rows
#pragma unroll
    for (int j = 0; j < 8; ++j) {
        const int row = row0 + j;
        const float4* wr =
            reinterpret_cast<const float4*>(W2o + (size_t)row * MID_);
        const float4 wa = wr[lane];
        const float4 wb = wr[32 + lane];
        float s = fmaf(wa.x, ya.x, fmaf(wa.y, ya.y,
                  fmaf(wa.z, ya.z, fmaf(wa.w, ya.w,
                  fmaf(wb.x, yb.x, fmaf(wb.y, yb.y,
                  fmaf(wb.z, yb.z, wb.w * yb.w)))))));
        s = warp_sum(s);
        if (lane == 0) {
            const float y2 = sigmoidf_(s + b2[o * MID_ + row]);
            p = fmaf(W3o[row], y2, p);
        }
    }

    __shared__ float sp[4];
    if (lane == 0) sp[warp] = p;
    __syncthreads();

    if (threadIdx.x == 0) {
        const float part = sp[0] + sp[1] + sp[2] + sp[3];
        atomicAdd(&g_acc[o], part);
        __threadfence();
        const unsigned c = atomicAdd(&g_cnt[o], 1u);
        if (c == 7u) {
            // All 8 partials are in (each add fenced before its counter bump).
            const float acc = *(volatile float*)&g_acc[o];
            out[o] = sigmoidf_(acc + b3[o]);
            g_acc[o] = 0.0f;   // reset for next graph replay
            g_cnt[o] = 0u;
        }
    }
}

extern "C" void kernel_launch(void* const* d_in, const int* in_sizes, int n_in,
                              void* d_out, int out_size)
{
    const float* x  = (const float*)d_in[0];
    const float* W1 = (const float*)d_in[1];
    const float* b1 = (const float*)d_in[2];
    const float* W2 = (const float*)d_in[3];
    const float* b2 = (const float*)d_in[4];
    const float* W3 = (const float*)d_in[5];
    const float* b3 = (const float*)d_in[6];
    float* out = (float*)d_out;

    k1_fc1<<<N_OBJ_ * 8, 128>>>(x, W1, b1);
    k2_fc2<<<N_OBJ_ * 8, 128>>>(W2, b2, W3, b3, out);
}

// round 5
// speedup vs baseline: 1.0674x; 1.0674x over previous
#include <cuda_runtime.h>

// Batched per-object 3-layer MLP — 3 sequential kernels, zero atomics/fences.
//
//   K1: y1 = W1 @ x + b1                          (256 MB stream, proven cfg)
//   K2: 32 rows of y2 per CTA; fold W3 dot for those rows; ONE plain store
//       of the partial to g_part[chunk][o]        (512 MB stream)
//   K3: out[o] = sigmoid(sum_c g_part[c][o] + b3) (64 KB, thread-per-object)
//
// Launch boundaries provide all ordering. Weights read exactly once,
// coalesced float4.

#define N_OBJ_  2048
#define IN_DIM_ 128
#define MID_    256

__device__ float g_y1[N_OBJ_ * MID_];
__device__ float g_part[8 * N_OBJ_];   // [chunk][object]

__device__ __forceinline__ float warp_sum(float v) {
#pragma unroll
    for (int off = 16; off > 0; off >>= 1)
        v += __shfl_xor_sync(0xffffffffu, v, off);
    return v;
}

__device__ __forceinline__ float sigmoidf_(float t) {
    return 1.0f / (1.0f + __expf(-t));
}

// ---- K1: 32 rows of y1 per CTA (4 warps x 8 rows) — identical to R2 ----
__global__ __launch_bounds__(128, 16)
void k1_fc1(const float* __restrict__ x,
            const float* __restrict__ W1,
            const float* __restrict__ b1)
{
    const int o     = blockIdx.x >> 3;
    const int chunk = blockIdx.x & 7;
    const int warp  = threadIdx.x >> 5;
    const int lane  = threadIdx.x & 31;

    const float4 xv =
        reinterpret_cast<const float4*>(x + (size_t)o * IN_DIM_)[lane];
    const float* W1o = W1 + (size_t)o * MID_ * IN_DIM_;
    const int row0 = chunk * 32 + warp * 8;

#pragma unroll
    for (int j = 0; j < 8; ++j) {
        const int row = row0 + j;
        const float4 w =
            reinterpret_cast<const float4*>(W1o + (size_t)row * IN_DIM_)[lane];
        float s = fmaf(w.x, xv.x, fmaf(w.y, xv.y, fmaf(w.z, xv.z, w.w * xv.w)));
        s = warp_sum(s);
        if (lane == 0)
            g_y1[o * MID_ + row] = s + b1[o * MID_ + row];
    }
}

// ---- K2: 32 rows of y2 per CTA + W3 partial; ONE plain store ----
__global__ __launch_bounds__(128, 16)
void k2_fc2(const float* __restrict__ W2,
            const float* __restrict__ b2,
            const float* __restrict__ W3)
{
    const int o     = blockIdx.x >> 3;
    const int chunk = blockIdx.x & 7;
    const int warp  = threadIdx.x >> 5;
    const int lane  = threadIdx.x & 31;

    const float4* y1v = reinterpret_cast<const float4*>(g_y1 + o * MID_);
    const float4 ya = y1v[lane];
    const float4 yb = y1v[32 + lane];

    const float* W2o = W2 + (size_t)o * MID_ * MID_;
    const float* W3o = W3 + (size_t)o * MID_;
    const int row0 = chunk * 32 + warp * 8;

    float p = 0.0f;   // lane-0 partial of W3 . y2 over this warp's 8 rows
#pragma unroll
    for (int j = 0; j < 8; ++j) {
        const int row = row0 + j;
        const float4* wr =
            reinterpret_cast<const float4*>(W2o + (size_t)row * MID_);
        const float4 wa = wr[lane];
        const float4 wb = wr[32 + lane];
        float s = fmaf(wa.x, ya.x, fmaf(wa.y, ya.y,
                  fmaf(wa.z, ya.z, fmaf(wa.w, ya.w,
                  fmaf(wb.x, yb.x, fmaf(wb.y, yb.y,
                  fmaf(wb.z, yb.z, wb.w * yb.w)))))));
        s = warp_sum(s);
        if (lane == 0) {
            const float y2 = sigmoidf_(s + b2[o * MID_ + row]);
            p = fmaf(W3o[row], y2, p);
        }
    }

    __shared__ float sp[4];
    if (lane == 0) sp[warp] = p;
    __syncthreads();
    if (threadIdx.x == 0)
        g_part[chunk * N_OBJ_ + o] = sp[0] + sp[1] + sp[2] + sp[3];
}

// ---- K3: thread-per-object reduction + sigmoid ----
__global__ __launch_bounds__(128)
void k3_final(const float* __restrict__ b3, float* __restrict__ out)
{
    const int o = blockIdx.x * 128 + threadIdx.x;
    float s = b3[o];
#pragma unroll
    for (int c = 0; c < 8; ++c)
        s += g_part[c * N_OBJ_ + o];
    out[o] = sigmoidf_(s);
}

extern "C" void kernel_launch(void* const* d_in, const int* in_sizes, int n_in,
                              void* d_out, int out_size)
{
    const float* x  = (const float*)d_in[0];
    const float* W1 = (const float*)d_in[1];
    const float* b1 = (const float*)d_in[2];
    const float* W2 = (const float*)d_in[3];
    const float* b2 = (const float*)d_in[4];
    const float* W3 = (const float*)d_in[5];
    const float* b3 = (const float*)d_in[6];
    float* out = (float*)d_out;

    k1_fc1<<<N_OBJ_ * 8, 128>>>(x, W1, b1);
    k2_fc2<<<N_OBJ_ * 8, 128>>>(W2, b2, W3);
    k3_final<<<N_OBJ_ / 128, 128>>>(b3, out);
}